// round 2
// baseline (speedup 1.0000x reference)
#include <cuda_runtime.h>
#include <math_constants.h>

#define BB 512
#define TT 1024
#define KK 48

__device__ int   g_msize;        // 1 = byte mask, 4 = 32-bit mask (int32/float32)
__device__ int   g_len[BB];
__device__ float g_score[BB];

// ---------------------------------------------------------------------------
// Kernel 0: probe mask element size. mask[0,1] is guaranteed true
// (lengths >= T/2), so bytes 1..3 of element 0 are nonzero iff 1-byte dtype.
// ---------------------------------------------------------------------------
__global__ void crf_probe_kernel(const unsigned char* __restrict__ m)
{
    g_msize = (m[1] | m[2] | m[3]) ? 1 : 4;
}

// ---------------------------------------------------------------------------
// Kernel 1: per-batch sequence length (mask is a monotone prefix).
// One warp per batch.
// ---------------------------------------------------------------------------
__global__ void __launch_bounds__(128) crf_len_kernel(const void* __restrict__ mask)
{
    int warp = threadIdx.x >> 5;
    int lane = threadIdx.x & 31;
    int b = blockIdx.x * 4 + warp;
    if (b >= BB) return;
    const int base = b * TT;
    const int msz = g_msize;

    int cnt = 0;
    if (msz == 1) {
        const unsigned char* m = (const unsigned char*)mask;
        #pragma unroll 4
        for (int t = lane; t < TT; t += 32) cnt += (m[base + t] != 0);
    } else {
        const unsigned int* m = (const unsigned int*)mask;
        #pragma unroll 4
        for (int t = lane; t < TT; t += 32) cnt += (m[base + t] != 0u);
    }
    #pragma unroll
    for (int o = 16; o; o >>= 1) cnt += __shfl_xor_sync(0xffffffffu, cnt, o);
    if (lane == 0) g_len[b] = cnt;
}

// ---------------------------------------------------------------------------
// Kernel 2: numerator score. One warp per batch.
// score[b] = start[tag0] + em[b,0,tag0]
//          + sum_{1<=t<len} (em[b,t,tag_t] + trans[tag_{t-1}, tag_t])
//          + end[tag_{len-1}]
// ---------------------------------------------------------------------------
__global__ void __launch_bounds__(128) crf_score_kernel(
    const float* __restrict__ em,
    const int* __restrict__ tags,
    const float* __restrict__ trans,
    const float* __restrict__ startt,
    const float* __restrict__ endt)
{
    int warp = threadIdx.x >> 5;
    int lane = threadIdx.x & 31;
    int b = blockIdx.x * 4 + warp;
    if (b >= BB) return;
    const int base = b * TT;
    const int len = g_len[b];

    float acc = 0.0f;
    for (int k = 0; k * 32 < len; k++) {
        int t = k * 32 + lane;
        if (t >= 1 && t < len) {
            int cur  = tags[base + t];
            int prev = tags[base + t - 1];
            acc += em[(size_t)(base + t) * KK + cur] + trans[prev * KK + cur];
        }
    }
    #pragma unroll
    for (int o = 16; o; o >>= 1) acc += __shfl_xor_sync(0xffffffffu, acc, o);
    if (lane == 0) {
        int tag0 = tags[base];
        float s = startt[tag0] + em[(size_t)base * KK + tag0] + acc;
        s += endt[tags[base + len - 1]];
        g_score[b] = s;
    }
}

// ---------------------------------------------------------------------------
// Kernel 3: forward algorithm (denominator) + final output.
// One block of 64 threads per batch; thread j owns alpha[j] (j < 48 active).
// Recurrence (matching reference exactly; note transposed transitions):
//   alpha_new[j] = lse_i(alpha[i] + trans[j,i]) + em[b,t,j]
// computed as  c + log( sum_i exp(alpha[i]-c) * eT[j][i] ) + em,
// with eT[j][i] = exp(trans[j*K+i]) held in registers (row j per thread),
// and c = alpha[0] of the previous step (cheap shared broadcast).
// ---------------------------------------------------------------------------
__global__ void __launch_bounds__(64) crf_forward_kernel(
    const float* __restrict__ em,
    const float* __restrict__ trans,
    const float* __restrict__ startt,
    const float* __restrict__ endt,
    float* __restrict__ out)
{
    const int b = blockIdx.x;
    const int j = threadIdx.x;            // 0..63, active j < KK
    const int jj = (j < KK) ? j : (KK - 1);
    const int len = g_len[b];

    __shared__ __align__(16) float p_sh[64];
    __shared__ float c_sh;
    __shared__ float red[64];

    // ---- load exp(transitions) row jj into registers (one-time) ----
    float eT[KK];
    #pragma unroll
    for (int i = 0; i < KK; i++) eT[i] = __expf(trans[jj * KK + i]);

    // ---- init alpha at t = 0 ----
    const size_t em_base = (size_t)b * TT * KK;
    float alpha = 0.0f;
    if (j < KK) alpha = startt[j] + em[em_base + j];
    if (j == 0) c_sh = alpha;

    // prefetch emission for t = 1
    float e_next = 0.0f;
    if (j < KK && len > 1) e_next = em[em_base + (size_t)KK + j];

    // ---- main scan: t = 1 .. len-1 (mask beyond len is all-false) ----
    for (int t = 1; t < len; t++) {
        __syncthreads();                  // S1: prev p consumed; c_sh visible
        float c = c_sh;
        p_sh[j] = __expf(alpha - c);
        float e = e_next;
        if (j < KK && t + 1 < len)
            e_next = em[em_base + (size_t)(t + 1) * KK + j];
        __syncthreads();                  // S2: p ready

        float s0 = 0.f, s1 = 0.f, s2 = 0.f, s3 = 0.f;
        #pragma unroll
        for (int i = 0; i < KK; i += 4) {
            float4 p4 = *(const float4*)(p_sh + i);   // broadcast LDS.128
            s0 = fmaf(p4.x, eT[i + 0], s0);
            s1 = fmaf(p4.y, eT[i + 1], s1);
            s2 = fmaf(p4.z, eT[i + 2], s2);
            s3 = fmaf(p4.w, eT[i + 3], s3);
        }
        float s = (s0 + s1) + (s2 + s3);

        alpha = c + __logf(s) + e;
        if (j == 0) c_sh = alpha;
    }

    // ---- log_den = lse_j(alpha[j] + end[j]);  out = score - log_den ----
    red[j] = (j < KK) ? (alpha + endt[j]) : -CUDART_INF_F;
    __syncthreads();
    if (j == 0) {
        float m = -CUDART_INF_F;
        #pragma unroll
        for (int i = 0; i < KK; i++) m = fmaxf(m, red[i]);
        float ssum = 0.0f;
        #pragma unroll
        for (int i = 0; i < KK; i++) ssum += __expf(red[i] - m);
        out[b] = g_score[b] - (m + __logf(ssum));
    }
}

extern "C" void kernel_launch(void* const* d_in, const int* in_sizes, int n_in,
                              void* d_out, int out_size)
{
    const float* em    = (const float*)d_in[0];
    const int*   tags  = (const int*)d_in[1];
    const void*  mask  = d_in[2];
    const float* trans = (const float*)d_in[3];
    const float* stt   = (const float*)d_in[4];
    const float* ent   = (const float*)d_in[5];
    float*       out   = (float*)d_out;

    crf_probe_kernel<<<1, 1>>>((const unsigned char*)mask);
    crf_len_kernel<<<BB / 4, 128>>>(mask);
    crf_score_kernel<<<BB / 4, 128>>>(em, tags, trans, stt, ent);
    crf_forward_kernel<<<BB, 64>>>(em, trans, stt, ent, out);
}

// round 3
// speedup vs baseline: 1.5794x; 1.5794x over previous
#include <cuda_runtime.h>
#include <math_constants.h>

#define BB 512
#define TT 1024
#define KK 48

__device__ int   g_len[BB];
__device__ float g_score[BB];

typedef unsigned long long ull;

__device__ __forceinline__ ull pack2(float lo, float hi) {
    return ((ull)__float_as_uint(hi) << 32) | (ull)__float_as_uint(lo);
}
__device__ __forceinline__ float unpack_lo(ull v) { return __uint_as_float((unsigned)v); }
__device__ __forceinline__ float unpack_hi(ull v) { return __uint_as_float((unsigned)(v >> 32)); }

#define FFMA2(d, a, b, c) asm("fma.rn.f32x2 %0, %1, %2, %3;" : "=l"(d) : "l"(a), "l"(b), "l"(c))

// ---------------------------------------------------------------------------
// Kernel 1: per-batch sequence length (mask is a monotone prefix).
// One warp per batch. Mask dtype sniffed from element 0 (mask[0,0]=true and
// mask[0,1]=true guaranteed since lengths >= T/2): bytes 1..3 nonzero <=> u8.
// ---------------------------------------------------------------------------
__global__ void __launch_bounds__(128) crf_len_kernel(const void* __restrict__ mask)
{
    int warp = threadIdx.x >> 5;
    int lane = threadIdx.x & 31;
    int b = blockIdx.x * 4 + warp;
    if (b >= BB) return;
    const unsigned char* mb = (const unsigned char*)mask;
    const bool bytemask = (mb[1] | mb[2] | mb[3]) != 0;

    int cnt = 0;
    if (bytemask) {
        const unsigned char* m = mb + b * TT;
        #pragma unroll 4
        for (int t = lane; t < TT; t += 32) cnt += (m[t] != 0);
    } else {
        const unsigned int* m = (const unsigned int*)mask + b * TT;
        #pragma unroll 4
        for (int t = lane; t < TT; t += 32) cnt += (m[t] != 0u);
    }
    #pragma unroll
    for (int o = 16; o; o >>= 1) cnt += __shfl_xor_sync(0xffffffffu, cnt, o);
    if (lane == 0) g_len[b] = cnt;
}

// ---------------------------------------------------------------------------
// Kernel 2: numerator score. One warp per batch.
// ---------------------------------------------------------------------------
__global__ void __launch_bounds__(128) crf_score_kernel(
    const float* __restrict__ em,
    const int* __restrict__ tags,
    const float* __restrict__ trans,
    const float* __restrict__ startt,
    const float* __restrict__ endt)
{
    int warp = threadIdx.x >> 5;
    int lane = threadIdx.x & 31;
    int b = blockIdx.x * 4 + warp;
    if (b >= BB) return;
    const int base = b * TT;
    const int len = g_len[b];

    float acc = 0.0f;
    for (int k = 0; k * 32 < len; k++) {
        int t = k * 32 + lane;
        if (t >= 1 && t < len) {
            int cur  = tags[base + t];
            int prev = tags[base + t - 1];
            acc += em[(size_t)(base + t) * KK + cur] + trans[prev * KK + cur];
        }
    }
    #pragma unroll
    for (int o = 16; o; o >>= 1) acc += __shfl_xor_sync(0xffffffffu, acc, o);
    if (lane == 0) {
        int tag0 = tags[base];
        float s = startt[tag0] + em[(size_t)base * KK + tag0] + acc;
        s += endt[tags[base + len - 1]];
        g_score[b] = s;
    }
}

// ---------------------------------------------------------------------------
// Kernel 3: forward algorithm. One 64-thread block per batch; thread j owns
// alpha[j] (threads 48..63 mirror state 47, write private slots, unread).
//
//   alpha_new[j] = c + log( sum_i exp(alpha[i]-c) * exp(trans[j,i]) ) + em[b,t,j]
//
// - exp(trans) row packed into 24 x f32x2 registers -> fma.rn.f32x2
// - shift c is alpha[0] from TWO steps ago -> single barrier/step with
//   double-buffered p_sh (write of c2[t&1] at step t is separated from its
//   readers at step t+2 by the barriers of steps t+1 and t+2)
// - emissions prefetched 8 steps deep, double-buffered in registers
// ---------------------------------------------------------------------------
__global__ void __launch_bounds__(64) crf_forward_kernel(
    const float* __restrict__ em,
    const float* __restrict__ trans,
    const float* __restrict__ startt,
    const float* __restrict__ endt,
    float* __restrict__ out)
{
    const int b = blockIdx.x;
    const int j = threadIdx.x;               // 0..63
    const int jj = (j < KK) ? j : (KK - 1);
    const int len = g_len[b];

    __shared__ __align__(16) float p_sh[2][64];
    __shared__ float c2[2];
    __shared__ float red[64];

    // exp(transitions) row jj, packed in pairs
    ull eT2[KK / 2];
    #pragma unroll
    for (int i = 0; i < KK / 2; i++)
        eT2[i] = pack2(__expf(trans[jj * KK + 2 * i]),
                       __expf(trans[jj * KK + 2 * i + 1]));

    const size_t em_base = (size_t)b * TT * KK;
    float alpha = startt[jj] + em[em_base + jj];
    if (j == 0) { c2[0] = alpha; c2[1] = alpha; }

    // preload emission group for t = 1..8
    float eb[2][8];
    #pragma unroll
    for (int s = 0; s < 8; s++) {
        int tt = 1 + s; tt = (tt < TT) ? tt : (TT - 1);
        eb[0][s] = em[em_base + (size_t)tt * KK + jj];
    }
    __syncthreads();

    int gi = 0;
    for (int t0 = 1; t0 < len; t0 += 8) {
        // prefetch next group (8 independent LDGs, consumed next group)
        #pragma unroll
        for (int s = 0; s < 8; s++) {
            int tt = t0 + 8 + s; tt = (tt < TT) ? tt : (TT - 1);
            eb[gi ^ 1][s] = em[em_base + (size_t)tt * KK + jj];
        }
        const int tend = (t0 + 8 < len) ? (t0 + 8) : len;

        #pragma unroll
        for (int s = 0; s < 8; s++) {
            const int t = t0 + s;
            if (t >= tend) break;
            const int pb = t & 1;

            float c = c2[pb];                       // alpha[0] from t-2
            p_sh[pb][j] = __expf(alpha - c);
            __syncthreads();                        // single barrier per step

            const double2* P = (const double2*)p_sh[pb];
            ull a0 = 0ULL, a1 = 0ULL, a2 = 0ULL, a3 = 0ULL;
            #pragma unroll
            for (int i = 0; i < 12; i += 2) {
                double2 q0 = P[i];
                double2 q1 = P[i + 1];
                FFMA2(a0, __double_as_longlong(q0.x), eT2[2 * i + 0], a0);
                FFMA2(a1, __double_as_longlong(q0.y), eT2[2 * i + 1], a1);
                FFMA2(a2, __double_as_longlong(q1.x), eT2[2 * i + 2], a2);
                FFMA2(a3, __double_as_longlong(q1.y), eT2[2 * i + 3], a3);
            }
            float ssum = ((unpack_lo(a0) + unpack_hi(a0)) + (unpack_lo(a1) + unpack_hi(a1)))
                       + ((unpack_lo(a2) + unpack_hi(a2)) + (unpack_lo(a3) + unpack_hi(a3)));

            alpha = c + __logf(ssum) + eb[gi][s];
            if (j == 0) c2[pb] = alpha;             // for step t+2
        }
        gi ^= 1;
    }

    // log_den = lse_j(alpha[j] + end[j]);  out = score - log_den
    red[j] = (j < KK) ? (alpha + endt[j]) : -CUDART_INF_F;
    __syncthreads();
    if (j == 0) {
        float m = -CUDART_INF_F;
        #pragma unroll
        for (int i = 0; i < KK; i++) m = fmaxf(m, red[i]);
        float ssum = 0.0f;
        #pragma unroll
        for (int i = 0; i < KK; i++) ssum += __expf(red[i] - m);
        out[b] = g_score[b] - (m + __logf(ssum));
    }
}

extern "C" void kernel_launch(void* const* d_in, const int* in_sizes, int n_in,
                              void* d_out, int out_size)
{
    const float* em    = (const float*)d_in[0];
    const int*   tags  = (const int*)d_in[1];
    const void*  mask  = d_in[2];
    const float* trans = (const float*)d_in[3];
    const float* stt   = (const float*)d_in[4];
    const float* ent   = (const float*)d_in[5];
    float*       out   = (float*)d_out;

    crf_len_kernel<<<BB / 4, 128>>>(mask);
    crf_score_kernel<<<BB / 4, 128>>>(em, tags, trans, stt, ent);
    crf_forward_kernel<<<BB, 64>>>(em, trans, stt, ent, out);
}

// round 4
// speedup vs baseline: 1.7866x; 1.1312x over previous
#include <cuda_runtime.h>
#include <math_constants.h>

#define BB 512
#define TT 1024
#define KK 48

typedef unsigned long long ull;

__device__ __forceinline__ ull pack2(float lo, float hi) {
    return ((ull)__float_as_uint(hi) << 32) | (ull)__float_as_uint(lo);
}
__device__ __forceinline__ float ulo(ull v){ return __uint_as_float((unsigned)v); }
__device__ __forceinline__ float uhi(ull v){ return __uint_as_float((unsigned)(v >> 32)); }

#define FFMA2(d,a,b,c) asm("fma.rn.f32x2 %0, %1, %2, %3;" : "=l"(d) : "l"(a), "l"(b), "l"(c))

// ---------------------------------------------------------------------------
// One block (32 threads, 1 warp) per batch. Lane j owns states j and j+32
// (j+32 >= 48 -> zero-padded row). Forward recurrence kept in LINEAR space:
//   q'_j = (sum_i q_i * exp(trans[j,i])) * exp(em[t,j]) * r
// with r a one-step-stale uniform rescale (cancels algebraically) and the
// log-scale C accumulated on a parallel scalar chain. exp/log never appear
// on the per-step critical path.
// ---------------------------------------------------------------------------
__global__ void __launch_bounds__(32) crf_fused_kernel(
    const float* __restrict__ em,
    const int*   __restrict__ tags,
    const void*  __restrict__ mask,
    const float* __restrict__ trans,
    const float* __restrict__ startt,
    const float* __restrict__ endt,
    float*       __restrict__ out)
{
    const int b  = blockIdx.x;
    const int j  = threadIdx.x;          // 0..31
    const int j2 = j + 32;               // second state (valid if < 48)
    const bool has2 = (j2 < KK);
    const int jc = has2 ? j2 : j;        // clamped index for safe loads

    __shared__ __align__(16) float sh[2][64];

    // ---- sequence length (mask is a monotone prefix; dtype sniffed:
    //      mask[0,1] guaranteed true since lengths >= T/2) ----
    const unsigned char* mb = (const unsigned char*)mask;
    int cnt = 0;
    if (mb[1] | mb[2] | mb[3]) {
        const unsigned char* m = mb + b * TT;
        #pragma unroll
        for (int t = j; t < TT; t += 32) cnt += (m[t] != 0);
    } else {
        const unsigned int* m = (const unsigned int*)mask + b * TT;
        #pragma unroll
        for (int t = j; t < TT; t += 32) cnt += (m[t] != 0u);
    }
    #pragma unroll
    for (int o = 16; o; o >>= 1) cnt += __shfl_xor_sync(0xffffffffu, cnt, o);
    const int len = cnt;

    const size_t em_base = (size_t)b * TT * KK;

    // ---- numerator score: independent gathers, deep MLP, warp-reduced ----
    float acc = 0.0f;
    {
        const int base = b * TT;
        for (int k = 0; k * 32 < len; k++) {
            int t = k * 32 + j;
            if (t >= 1 && t < len) {
                int cur  = tags[base + t];
                int prev = tags[base + t - 1];
                acc += em[em_base + (size_t)t * KK + cur] + trans[prev * KK + cur];
            }
        }
        #pragma unroll
        for (int o = 16; o; o >>= 1) acc += __shfl_xor_sync(0xffffffffu, acc, o);
    }

    // ---- exp(transitions) rows for both owned states (packed f32x2) ----
    ull eTa[24], eTb[24];
    #pragma unroll
    for (int i = 0; i < 24; i++) {
        eTa[i] = pack2(__expf(trans[j * KK + 2 * i]),
                       __expf(trans[j * KK + 2 * i + 1]));
        eTb[i] = has2 ? pack2(__expf(trans[j2 * KK + 2 * i]),
                              __expf(trans[j2 * KK + 2 * i + 1]))
                      : 0ULL;
    }
    float eend0 = __expf(endt[j]);
    float eend1 = has2 ? __expf(endt[jc]) : 0.0f;

    // ---- init t = 0 :  q_j = exp(alpha0_j - alpha0_0),  C = alpha0_0 ----
    float a00 = startt[j] + em[em_base + j];
    float c0  = __shfl_sync(0xffffffffu, a00, 0);
    float q0v = __expf(a00 - c0);                         // lane0 -> exactly 1
    float q1v = has2 ? __expf(startt[jc] + em[em_base + jc] - c0) : 0.0f;
    sh[0][j]  = q0v;
    sh[0][j2] = q1v;
    float C = c0, r = 1.0f, xcur = 1.0f;
    __syncthreads();

    // ---- emission exp prefetch buffers (8 steps deep, double-buffered) ----
    float eA0[8], eA1[8], eB0[8], eB1[8];
    #pragma unroll
    for (int s = 0; s < 8; s++) {
        int tt = 1 + s; tt = (tt < TT) ? tt : (TT - 1);
        eA0[s] = __expf(em[em_base + (size_t)tt * KK + j]);
        eA1[s] = __expf(em[em_base + (size_t)tt * KK + jc]);
    }

#define DOT_AND_UPDATE(RD, WR, EE0, EE1) do {                                  \
    const double2* P2 = (const double2*)sh[RD];                                \
    ull A0=0,A1=0,A2=0,A3=0,B0=0,B1=0,B2=0,B3=0;                               \
    _Pragma("unroll")                                                          \
    for (int i = 0; i < 12; i += 2) {                                          \
        double2 qA = P2[i]; double2 qB = P2[i + 1];                            \
        ull xa=__double_as_longlong(qA.x), xb=__double_as_longlong(qA.y);      \
        ull xc=__double_as_longlong(qB.x), xd=__double_as_longlong(qB.y);      \
        FFMA2(A0, xa, eTa[2*i+0], A0);  FFMA2(A1, xb, eTa[2*i+1], A1);         \
        FFMA2(A2, xc, eTa[2*i+2], A2);  FFMA2(A3, xd, eTa[2*i+3], A3);         \
        FFMA2(B0, xa, eTb[2*i+0], B0);  FFMA2(B1, xb, eTb[2*i+1], B1);         \
        FFMA2(B2, xc, eTb[2*i+2], B2);  FFMA2(B3, xd, eTb[2*i+3], B3);         \
    }                                                                          \
    float u0 = ((ulo(A0)+uhi(A0)) + (ulo(A1)+uhi(A1)))                         \
             + ((ulo(A2)+uhi(A2)) + (ulo(A3)+uhi(A3)));                        \
    float u1 = ((ulo(B0)+uhi(B0)) + (ulo(B1)+uhi(B1)))                         \
             + ((ulo(B2)+uhi(B2)) + (ulo(B3)+uhi(B3)));                        \
    C += __logf(xcur);               /* scalar side-chain, lags main chain */  \
    q0v = u0 * (EE0) * r;                                                      \
    q1v = u1 * (EE1) * r;                                                      \
    sh[WR][j]  = q0v;                                                          \
    sh[WR][j2] = q1v;                                                          \
    xcur = __shfl_sync(0xffffffffu, q0v, 0);                                   \
    __syncthreads();                 /* nw=1 barrier: ~3 cyc */                \
    r = __fdividef(1.0f, xcur);      /* stale rescale, off-chain */            \
} while (0)

    // t0 stays odd across groups -> s even reads buf0/writes buf1, s odd swaps
    int t0 = 1;
    while (t0 < len) {
        #pragma unroll
        for (int s = 0; s < 8; s++) {
            int tt = t0 + 8 + s; tt = (tt < TT) ? tt : (TT - 1);
            eB0[s] = __expf(em[em_base + (size_t)tt * KK + j]);
            eB1[s] = __expf(em[em_base + (size_t)tt * KK + jc]);
        }
        {
            const int tend = (t0 + 8 < len) ? (t0 + 8) : len;
            #pragma unroll
            for (int s = 0; s < 8; s++) {
                if (t0 + s >= tend) break;
                if (s & 1) DOT_AND_UPDATE(1, 0, eA0[s], eA1[s]);
                else       DOT_AND_UPDATE(0, 1, eA0[s], eA1[s]);
            }
        }
        t0 += 8;
        if (t0 >= len) break;

        #pragma unroll
        for (int s = 0; s < 8; s++) {
            int tt = t0 + 8 + s; tt = (tt < TT) ? tt : (TT - 1);
            eA0[s] = __expf(em[em_base + (size_t)tt * KK + j]);
            eA1[s] = __expf(em[em_base + (size_t)tt * KK + jc]);
        }
        {
            const int tend = (t0 + 8 < len) ? (t0 + 8) : len;
            #pragma unroll
            for (int s = 0; s < 8; s++) {
                if (t0 + s >= tend) break;
                if (s & 1) DOT_AND_UPDATE(1, 0, eB0[s], eB1[s]);
                else       DOT_AND_UPDATE(0, 1, eB0[s], eB1[s]);
            }
        }
        t0 += 8;
    }
#undef DOT_AND_UPDATE

    // ---- log_den = C + log( sum_j q_j * exp(end_j) );  out = score - den ----
    float tot = q0v * eend0 + q1v * eend1;
    #pragma unroll
    for (int o = 16; o; o >>= 1) tot += __shfl_xor_sync(0xffffffffu, tot, o);

    if (j == 0) {
        const int base = b * TT;
        int tag0 = tags[base];
        float score = startt[tag0] + em[em_base + tag0] + acc
                    + endt[tags[base + len - 1]];
        out[b] = score - (C + __logf(tot));
    }
}

extern "C" void kernel_launch(void* const* d_in, const int* in_sizes, int n_in,
                              void* d_out, int out_size)
{
    const float* em    = (const float*)d_in[0];
    const int*   tags  = (const int*)d_in[1];
    const void*  mask  = d_in[2];
    const float* trans = (const float*)d_in[3];
    const float* stt   = (const float*)d_in[4];
    const float* ent   = (const float*)d_in[5];
    float*       out   = (float*)d_out;

    crf_fused_kernel<<<BB, 32>>>(em, tags, mask, trans, stt, ent, out);
}